// round 3
// baseline (speedup 1.0000x reference)
#include <cuda_runtime.h>
#include <math.h>

#define S_MAX   360
#define EPS_CLP 1e-6f
#define FULL    0xFFFFFFFFu

// dot(u, qua_mul(y, q)) == v . q  with v = M(y)^T u (M orthogonal), so each
// symmetry element costs one 4-wide dot after a 16-FMA per-sample setup.
// Tie-breaking replicates jnp.argmin over concat([acos(d), acos(-d)]):
// clamp before compare, lowest index wins, half0 beats half1 on equal value.

__device__ __forceinline__ void compute_v(const float4 xv, const float4 yv,
                                          float& vx, float& vy, float& vz, float& vw)
{
    const float inv = rsqrtf(xv.x*xv.x + xv.y*xv.y + xv.z*xv.z + xv.w*xv.w);
    const float ux = xv.x*inv, uy = xv.y*inv, uz = xv.z*inv, uw = xv.w*inv;
    const float px = yv.x, py = yv.y, pz = yv.z, pw = yv.w;
    vx =  ux*pw - uy*pz + uz*py - uw*px;
    vy =  ux*pz + uy*pw - uz*px - uw*py;
    vz = -ux*py + uy*px + uz*pw - uw*pz;
    vw =  ux*px + uy*py + uz*pz + uw*pw;
}

__device__ __forceinline__ void write_result(float* __restrict__ out, int B, int b,
                                             const float4 xv, const float4 yv,
                                             const float4 q,
                                             float vbest, bool half0)
{
    const float loss = acosf(vbest);
    // pos = qua_mul(y, q), exactly the reference formula (xyzw, w last)
    const float px = yv.x, py = yv.y, pz = yv.z, pw = yv.w;
    const float qx = q.x,  qy = q.y,  qz = q.z,  qw = q.w;
    const float rw = qw*pw - qx*px - qy*py - qz*pz;
    const float rx = qw*px + qx*pw + qy*pz - qz*py;
    const float ry = qw*py - qx*pz + qy*pw + qz*px;
    const float rz = qw*pz + qx*py - qy*px + qz*pw;
    const float sgn = half0 ? 1.0f : -1.0f;

    out[b] = loss;
    reinterpret_cast<float4*>(out + B)[b]   = make_float4(xv.x*sgn, xv.y*sgn, xv.z*sgn, xv.w*sgn);
    reinterpret_cast<float4*>(out + 5*B)[b] = make_float4(rx, ry, rz, rw);
}

// ---------------- K1: thread-per-sample, classes 0..3 (c = 1,2,4,12) --------
__global__ __launch_bounds__(128)
void quer_small_kernel(const float*  __restrict__ x,
                       const float*  __restrict__ y,
                       const int*    __restrict__ n,
                       const float4* __restrict__ sym,   // [5*360] float4
                       float* __restrict__ out, int B)
{
    __shared__ float4 ssym[4 * 12];   // classes 0..3, first 12 entries each
    const int tid = threadIdx.x;
    if (tid < 48)
        ssym[tid] = __ldg(sym + (tid / 12) * S_MAX + (tid % 12));
    __syncthreads();

    const int b = blockIdx.x * 128 + tid;
    if (b >= B) return;

    const int cls = __ldg(n + b);
    if (cls == 4) return;             // handled by K2

    const int c = (cls == 0) ? 1 : (cls == 1) ? 2 : (cls == 2) ? 4 : 12;

    const float4 xv = __ldg(reinterpret_cast<const float4*>(x) + b);
    const float4 yv = __ldg(reinterpret_cast<const float4*>(y) + b);
    float vx, vy, vz, vw;
    compute_v(xv, yv, vx, vy, vz, vw);

    const float4* __restrict__ tab = ssym + cls * 12;
    float best0 = -2.0f, best1 = -2.0f;
    int   i0 = 0, i1 = 0;
    for (int s = 0; s < c; ++s) {
        const float4 q = tab[s];
        float d = vx*q.x + vy*q.y + vz*q.z + vw*q.w;
        d = fminf(fmaxf(d, -1.0f + EPS_CLP), 1.0f - EPS_CLP);
        if ( d > best0) { best0 =  d; i0 = s; }   // strict > keeps lowest s
        if (-d > best1) { best1 = -d; i1 = s; }
    }

    const bool  half0 = (best0 >= best1);
    const float vbest = half0 ? best0 : best1;
    const int   sbest = half0 ? i0 : i1;
    write_result(out, B, b, xv, yv, tab[sbest], vbest, half0);
}

// ---------------- K2: warp-per-sample, class 4 (c = 360) --------------------
__global__ __launch_bounds__(256)
void quer_360_kernel(const float*  __restrict__ x,
                     const float*  __restrict__ y,
                     const int*    __restrict__ n,
                     const float4* __restrict__ sym,
                     float* __restrict__ out, int B)
{
    const int w    = (blockIdx.x * blockDim.x + threadIdx.x) >> 5;
    const int lane = threadIdx.x & 31;
    if (w >= B) return;
    const int b = w;

    if (__ldg(n + b) != 4) return;    // warp-uniform: one sample per warp

    const float4 xv = __ldg(reinterpret_cast<const float4*>(x) + b);  // broadcast
    const float4 yv = __ldg(reinterpret_cast<const float4*>(y) + b);
    float vx, vy, vz, vw;
    compute_v(xv, yv, vx, vy, vz, vw);

    const float4* __restrict__ tab = sym + 4 * S_MAX;
    float best0 = -2.0f, best1 = -2.0f;
    int   i0 = lane, i1 = lane;
    #pragma unroll
    for (int k = 0; k < 12; ++k) {
        const int s = lane + k * 32;
        if (s < S_MAX) {
            const float4 q = __ldg(tab + s);
            float d = vx*q.x + vy*q.y + vz*q.z + vw*q.w;
            d = fminf(fmaxf(d, -1.0f + EPS_CLP), 1.0f - EPS_CLP);
            if ( d > best0) { best0 =  d; i0 = s; }
            if (-d > best1) { best1 = -d; i1 = s; }
        }
    }

    // warp argmax: higher value wins; tie -> lower index
    #pragma unroll
    for (int off = 16; off > 0; off >>= 1) {
        const float t0 = __shfl_down_sync(FULL, best0, off);
        const int   k0 = __shfl_down_sync(FULL, i0,    off);
        if (t0 > best0 || (t0 == best0 && k0 < i0)) { best0 = t0; i0 = k0; }
        const float t1 = __shfl_down_sync(FULL, best1, off);
        const int   k1 = __shfl_down_sync(FULL, i1,    off);
        if (t1 > best1 || (t1 == best1 && k1 < i1)) { best1 = t1; i1 = k1; }
    }

    if (lane == 0) {
        const bool  half0 = (best0 >= best1);
        const float vbest = half0 ? best0 : best1;
        const int   sbest = half0 ? i0 : i1;
        write_result(out, B, b, xv, yv, __ldg(tab + sbest), vbest, half0);
    }
}

extern "C" void kernel_launch(void* const* d_in, const int* in_sizes, int n_in,
                              void* d_out, int out_size)
{
    // metadata order: x[B,4], y[B,4], pred_n[B,5] (unused), n[B],
    //                 sym_qua[5,360,4], sym_mask[5,360] (unused)
    const float*  x   = (const float*) d_in[0];
    const float*  y   = (const float*) d_in[1];
    const int*    n   = (const int*)   d_in[3];
    const float4* sym = (const float4*)d_in[4];
    float* out = (float*)d_out;

    const int B = in_sizes[3];   // 65536

    quer_small_kernel<<<(B + 127) / 128, 128>>>(x, y, n, sym, out, B);
    // one warp per sample: B warps = B*32 threads
    const long long threads = (long long)B * 32;
    quer_360_kernel<<<(unsigned)((threads + 255) / 256), 256>>>(x, y, n, sym, out, B);
}

// round 4
// speedup vs baseline: 1.1342x; 1.1342x over previous
#include <cuda_runtime.h>
#include <math.h>

#define S_MAX   360
#define EPS_CLP 1e-6f
#define FULL    0xFFFFFFFFu
#define MAXB    65536

__device__ int d_count;
__device__ int d_idx[MAXB];

// dot(u, qua_mul(y, q)) == v . q  with v = M(y)^T u (M orthogonal).
// Tie-breaking replicates jnp.argmin over concat([acos(d), acos(-d)]):
// clamp before compare, lowest index wins, half0 beats half1 on equal value.

__device__ __forceinline__ void compute_v(const float4 xv, const float4 yv,
                                          float& vx, float& vy, float& vz, float& vw)
{
    const float inv = rsqrtf(xv.x*xv.x + xv.y*xv.y + xv.z*xv.z + xv.w*xv.w);
    const float ux = xv.x*inv, uy = xv.y*inv, uz = xv.z*inv, uw = xv.w*inv;
    const float px = yv.x, py = yv.y, pz = yv.z, pw = yv.w;
    vx =  ux*pw - uy*pz + uz*py - uw*px;
    vy =  ux*pz + uy*pw - uz*px - uw*py;
    vz = -ux*py + uy*px + uz*pw - uw*pz;
    vw =  ux*px + uy*py + uz*pz + uw*pw;
}

__device__ __forceinline__ void write_result(float* __restrict__ out, int B, int b,
                                             const float4 xv, const float4 yv,
                                             const float4 q, float vbest, bool half0,
                                             bool do_store)
{
    const float loss = acosf(vbest);
    const float px = yv.x, py = yv.y, pz = yv.z, pw = yv.w;
    const float qx = q.x,  qy = q.y,  qz = q.z,  qw = q.w;
    const float rw = qw*pw - qx*px - qy*py - qz*pz;
    const float rx = qw*px + qx*pw + qy*pz - qz*py;
    const float ry = qw*py - qx*pz + qy*pw + qz*px;
    const float rz = qw*pz + qx*py - qy*px + qz*pw;
    const float sgn = half0 ? 1.0f : -1.0f;
    if (do_store) {
        out[b] = loss;
        reinterpret_cast<float4*>(out + B)[b]   = make_float4(xv.x*sgn, xv.y*sgn, xv.z*sgn, xv.w*sgn);
        reinterpret_cast<float4*>(out + 5*B)[b] = make_float4(rx, ry, rz, rw);
    }
}

// monotone float<->int key (total order matching float compare, no NaNs here)
__device__ __forceinline__ int   f2ord(float f) { int b = __float_as_int(f); return b ^ ((b >> 31) & 0x7fffffff); }
__device__ __forceinline__ float ord2f(int k)   { return __int_as_float(k ^ ((k >> 31) & 0x7fffffff)); }

__global__ void zero_kernel() { d_count = 0; }

// ---- K0: small classes computed in-place; class-4 indices compacted --------
__global__ __launch_bounds__(256)
void quer_small_collect(const float*  __restrict__ x,
                        const float*  __restrict__ y,
                        const int*    __restrict__ n,
                        const float4* __restrict__ sym,
                        float* __restrict__ out, int B)
{
    __shared__ float4 ssym[4 * 12];
    const int tid  = threadIdx.x;
    const int lane = tid & 31;
    if (tid < 48)
        ssym[tid] = __ldg(sym + (tid / 12) * S_MAX + (tid % 12));
    __syncthreads();

    const int b = blockIdx.x * 256 + tid;
    const bool valid = (b < B);
    const int cls = valid ? __ldg(n + b) : 0;

    // warp-aggregated compaction of class-4 samples
    const bool big = valid && (cls == 4);
    const unsigned m = __ballot_sync(FULL, big);
    if (m) {
        int base = 0;
        if (lane == (__ffs(m) - 1))
            base = atomicAdd(&d_count, __popc(m));
        base = __shfl_sync(FULL, base, __ffs(m) - 1);
        if (big)
            d_idx[base + __popc(m & ((1u << lane) - 1))] = b;
    }

    if (!valid || big) return;

    const int c = (cls == 0) ? 1 : (cls == 1) ? 2 : (cls == 2) ? 4 : 12;

    const float4 xv = __ldg(reinterpret_cast<const float4*>(x) + b);
    const float4 yv = __ldg(reinterpret_cast<const float4*>(y) + b);
    float vx, vy, vz, vw;
    compute_v(xv, yv, vx, vy, vz, vw);

    const float4* __restrict__ tab = ssym + cls * 12;
    float best0 = -2.0f, best1 = -2.0f;
    int   i0 = 0, i1 = 0;
    for (int s = 0; s < c; ++s) {
        const float4 q = tab[s];
        float d = vx*q.x + vy*q.y + vz*q.z + vw*q.w;
        d = fminf(fmaxf(d, -1.0f + EPS_CLP), 1.0f - EPS_CLP);
        if ( d > best0) { best0 =  d; i0 = s; }
        if (-d > best1) { best1 = -d; i1 = s; }
    }

    const bool  half0 = (best0 >= best1);
    const float vbest = half0 ? best0 : best1;
    const int   sbest = half0 ? i0 : i1;
    write_result(out, B, b, xv, yv, tab[sbest], vbest, half0, true);
}

// ---- K2: class-4 (c=360), 4 compacted samples per warp, table in registers -
__global__ __launch_bounds__(256)
void quer_360_kernel(const float*  __restrict__ x,
                     const float*  __restrict__ y,
                     const float4* __restrict__ sym,
                     float* __restrict__ out, int B)
{
    const int w    = (blockIdx.x * blockDim.x + threadIdx.x) >> 5;
    const int lane = threadIdx.x & 31;
    const int count = d_count;
    const int base = w * 4;
    if (base >= count) return;

    const float4* __restrict__ tab = sym + 4 * S_MAX;

    // per-lane table slice in registers, reused across 4 samples
    float4 tq[12];
    #pragma unroll
    for (int k = 0; k < 12; ++k) {
        const int s = lane + k * 32;
        tq[k] = __ldg(tab + (s < S_MAX ? s : S_MAX - 1));
    }

    #pragma unroll
    for (int j = 0; j < 4; ++j) {
        if (base + j >= count) break;            // warp-uniform
        const int b = d_idx[base + j];           // broadcast load

        const float4 xv = __ldg(reinterpret_cast<const float4*>(x) + b);
        const float4 yv = __ldg(reinterpret_cast<const float4*>(y) + b);
        float vx, vy, vz, vw;
        compute_v(xv, yv, vx, vy, vz, vw);       // uniform across lanes

        float best0 = -2.0f, best1 = -2.0f;
        int   i0 = 0, i1 = 0;
        #pragma unroll
        for (int k = 0; k < 12; ++k) {
            const int s = lane + k * 32;
            const float4 q = tq[k];
            float d = vx*q.x + vy*q.y + vz*q.z + vw*q.w;
            d = fminf(fmaxf(d, -1.0f + EPS_CLP), 1.0f - EPS_CLP);
            const bool ok = (s < S_MAX);
            if (ok &&  d > best0) { best0 =  d; i0 = s; }
            if (ok && -d > best1) { best1 = -d; i1 = s; }
        }

        // warp argmax via redux: max key, then min index among lanes at max
        const int k0 = f2ord(best0);
        const int m0 = __reduce_max_sync(FULL, k0);
        const int s0 = __reduce_min_sync(FULL, (k0 == m0) ? i0 : 0x7fffffff);
        const float v0 = ord2f(m0);

        const int k1 = f2ord(best1);
        const int m1 = __reduce_max_sync(FULL, k1);
        const int s1 = __reduce_min_sync(FULL, (k1 == m1) ? i1 : 0x7fffffff);
        const float v1 = ord2f(m1);

        const bool  half0 = (v0 >= v1);
        const float vbest = half0 ? v0 : v1;
        const int   sbest = half0 ? s0 : s1;

        // uniform epilogue computation; lane 0 stores
        write_result(out, B, b, xv, yv, __ldg(tab + sbest), vbest, half0, lane == 0);
    }
}

extern "C" void kernel_launch(void* const* d_in, const int* in_sizes, int n_in,
                              void* d_out, int out_size)
{
    // metadata order: x[B,4], y[B,4], pred_n[B,5] (unused), n[B],
    //                 sym_qua[5,360,4], sym_mask[5,360] (unused)
    const float*  x   = (const float*) d_in[0];
    const float*  y   = (const float*) d_in[1];
    const int*    n   = (const int*)   d_in[3];
    const float4* sym = (const float4*)d_in[4];
    float* out = (float*)d_out;

    const int B = in_sizes[3];   // 65536

    zero_kernel<<<1, 1>>>();
    quer_small_collect<<<(B + 255) / 256, 256>>>(x, y, n, sym, out, B);

    // worst case: all B samples are class 4 -> B/4 warps
    const int warps  = (B + 3) / 4;
    const int blocks = (warps * 32 + 255) / 256;
    quer_360_kernel<<<blocks, 256>>>(x, y, sym, out, B);
}

// round 5
// speedup vs baseline: 1.1385x; 1.0038x over previous
#include <cuda_runtime.h>
#include <math.h>

#define S_MAX   360
#define EPS_CLP 1e-6f
#define FULL    0xFFFFFFFFu
#define SPW     8          // samples per warp

// dot(u, qua_mul(y, q)) == v . q  with v = M(y)^T u (M orthogonal), so each
// symmetry element costs one 4-wide dot after a 16-FMA per-sample setup.
// Tie-breaking replicates jnp.argmin over concat([acos(d), acos(-d)]):
// clamp before compare, lowest index wins, half0 beats half1 on equal value.

__device__ __forceinline__ void compute_v(const float4 xv, const float4 yv,
                                          float& vx, float& vy, float& vz, float& vw)
{
    const float inv = rsqrtf(xv.x*xv.x + xv.y*xv.y + xv.z*xv.z + xv.w*xv.w);
    const float ux = xv.x*inv, uy = xv.y*inv, uz = xv.z*inv, uw = xv.w*inv;
    const float px = yv.x, py = yv.y, pz = yv.z, pw = yv.w;
    vx =  ux*pw - uy*pz + uz*py - uw*px;
    vy =  ux*pz + uy*pw - uz*px - uw*py;
    vz = -ux*py + uy*px + uz*pw - uw*pz;
    vw =  ux*px + uy*py + uz*pz + uw*pw;
}

__device__ __forceinline__ void write_result(float* __restrict__ out, int B, int b,
                                             const float4 xv, const float4 yv,
                                             const float4 q, float vbest, bool half0)
{
    const float loss = acosf(vbest);
    const float px = yv.x, py = yv.y, pz = yv.z, pw = yv.w;
    const float qx = q.x,  qy = q.y,  qz = q.z,  qw = q.w;
    const float rw = qw*pw - qx*px - qy*py - qz*pz;
    const float rx = qw*px + qx*pw + qy*pz - qz*py;
    const float ry = qw*py - qx*pz + qy*pw + qz*px;
    const float rz = qw*pz + qx*py - qy*px + qz*pw;
    const float sgn = half0 ? 1.0f : -1.0f;
    out[b] = loss;
    reinterpret_cast<float4*>(out + B)[b]   = make_float4(xv.x*sgn, xv.y*sgn, xv.z*sgn, xv.w*sgn);
    reinterpret_cast<float4*>(out + 5*B)[b] = make_float4(rx, ry, rz, rw);
}

// monotone float<->int key (total order matching float compare; no NaNs here)
__device__ __forceinline__ int   f2ord(float f) { int b = __float_as_int(f); return b ^ ((b >> 31) & 0x7fffffff); }
__device__ __forceinline__ float ord2f(int k)   { return __int_as_float(k ^ ((k >> 31) & 0x7fffffff)); }

__global__ __launch_bounds__(256)
void quer_loss_kernel(const float*  __restrict__ x,
                      const float*  __restrict__ y,
                      const int*    __restrict__ n,
                      const float4* __restrict__ sym,   // [5*360] float4
                      float* __restrict__ out, int B)
{
    const int warp = (blockIdx.x * blockDim.x + threadIdx.x) >> 5;
    const int lane = threadIdx.x & 31;
    const int base = warp * SPW;
    if (base >= B) return;

    const float4* __restrict__ tab4 = sym + 4 * S_MAX;

    // per-lane slice of class-4 table in registers (reused across big samples)
    float4 tq[12];
    #pragma unroll
    for (int k = 0; k < 12; ++k) {
        const int s = lane + k * 32;
        tq[k] = __ldg(tab4 + (s < S_MAX ? s : 0));
    }

    // ---- per-lane sample state: lanes 0..SPW-1 each own one sample ----
    const int  b     = base + lane;
    const bool owner = (lane < SPW) && (b < B);

    float4 xv = make_float4(0,0,0,1), yv = make_float4(0,0,0,1);
    int cls = 0;
    if (owner) {
        xv  = __ldg(reinterpret_cast<const float4*>(x) + b);
        yv  = __ldg(reinterpret_cast<const float4*>(y) + b);
        cls = __ldg(n + b);
    }
    float vx, vy, vz, vw;
    compute_v(xv, yv, vx, vy, vz, vw);

    // ---- small-class phase: owning lanes scan their own c<=12 set ----
    if (owner && cls != 4) {
        const int c = (cls == 0) ? 1 : (cls == 1) ? 2 : (cls == 2) ? 4 : 12;
        const float4* __restrict__ tab = sym + cls * S_MAX;
        float best0 = -2.0f, best1 = -2.0f;
        int   i0 = 0, i1 = 0;
        for (int s = 0; s < c; ++s) {
            const float4 q = __ldg(tab + s);
            float d = vx*q.x + vy*q.y + vz*q.z + vw*q.w;
            d = fminf(fmaxf(d, -1.0f + EPS_CLP), 1.0f - EPS_CLP);
            if ( d > best0) { best0 =  d; i0 = s; }   // strict > keeps lowest s
            if (-d > best1) { best1 = -d; i1 = s; }
        }
        const bool  half0 = (best0 >= best1);
        const float vbest = half0 ? best0 : best1;
        const int   sbest = half0 ? i0 : i1;
        write_result(out, B, b, xv, yv, __ldg(tab + sbest), vbest, half0);
    }

    // ---- cooperative phase: whole warp scans each c==360 sample ----
    unsigned m = __ballot_sync(FULL, owner && cls == 4);
    while (m) {
        const int leader = __ffs(m) - 1;
        m &= m - 1;

        const float wvx = __shfl_sync(FULL, vx, leader);
        const float wvy = __shfl_sync(FULL, vy, leader);
        const float wvz = __shfl_sync(FULL, vz, leader);
        const float wvw = __shfl_sync(FULL, vw, leader);

        float best0 = -2.0f, best1 = -2.0f;
        int   i0 = 0, i1 = 0;
        #pragma unroll
        for (int k = 0; k < 12; ++k) {
            const int s = lane + k * 32;
            const float4 q = tq[k];
            float d = wvx*q.x + wvy*q.y + wvz*q.z + wvw*q.w;
            d = fminf(fmaxf(d, -1.0f + EPS_CLP), 1.0f - EPS_CLP);
            const bool ok = (s < S_MAX);
            if (ok &&  d > best0) { best0 =  d; i0 = s; }
            if (ok && -d > best1) { best1 = -d; i1 = s; }
        }

        // warp argmax via redux: max key, then min index among lanes at max
        const int k0 = f2ord(best0);
        const int mx0 = __reduce_max_sync(FULL, k0);
        const int s0  = __reduce_min_sync(FULL, (k0 == mx0) ? i0 : 0x7fffffff);
        const int k1 = f2ord(best1);
        const int mx1 = __reduce_max_sync(FULL, k1);
        const int s1  = __reduce_min_sync(FULL, (k1 == mx1) ? i1 : 0x7fffffff);

        if (lane == leader) {
            const float v0 = ord2f(mx0), v1 = ord2f(mx1);
            const bool  half0 = (v0 >= v1);
            const float vbest = half0 ? v0 : v1;
            const int   sbest = half0 ? s0 : s1;
            write_result(out, B, b, xv, yv, __ldg(tab4 + sbest), vbest, half0);
        }
    }
}

extern "C" void kernel_launch(void* const* d_in, const int* in_sizes, int n_in,
                              void* d_out, int out_size)
{
    // metadata order: x[B,4], y[B,4], pred_n[B,5] (unused), n[B],
    //                 sym_qua[5,360,4], sym_mask[5,360] (unused)
    const float*  x   = (const float*) d_in[0];
    const float*  y   = (const float*) d_in[1];
    const int*    n   = (const int*)   d_in[3];
    const float4* sym = (const float4*)d_in[4];
    float* out = (float*)d_out;

    const int B = in_sizes[3];                       // 65536
    const int warps  = (B + SPW - 1) / SPW;          // 8192 warps
    const int blocks = (warps * 32 + 255) / 256;     // 1024 blocks of 8 warps
    quer_loss_kernel<<<blocks, 256>>>(x, y, n, sym, out, B);
}

// round 6
// speedup vs baseline: 1.2931x; 1.1358x over previous
#include <cuda_runtime.h>
#include <math.h>

#define S_MAX   360
#define EPS_CLP 1e-6f
#define FULL    0xFFFFFFFFu
#define SPW     8          // samples per warp (lanes 0..7 own one each)

// dot(u, qua_mul(y, q)) == v . q  with v = M(y)^T u (M orthogonal), so each
// symmetry element costs one 4-wide dot after a 16-FMA per-sample setup.
// Tie-breaking replicates jnp.argmin over concat([acos(d), acos(-d)]):
// clamp before compare, lowest index wins, half0 beats half1 on equal value.

__device__ __forceinline__ void compute_v(const float4 xv, const float4 yv,
                                          float& vx, float& vy, float& vz, float& vw)
{
    const float inv = rsqrtf(xv.x*xv.x + xv.y*xv.y + xv.z*xv.z + xv.w*xv.w);
    const float ux = xv.x*inv, uy = xv.y*inv, uz = xv.z*inv, uw = xv.w*inv;
    const float px = yv.x, py = yv.y, pz = yv.z, pw = yv.w;
    vx =  ux*pw - uy*pz + uz*py - uw*px;
    vy =  ux*pz + uy*pw - uz*px - uw*py;
    vz = -ux*py + uy*px + uz*pw - uw*pz;
    vw =  ux*px + uy*py + uz*pz + uw*pw;
}

__device__ __forceinline__ void write_result(float* __restrict__ out, int B, int b,
                                             const float4 xv, const float4 yv,
                                             const float4 q, float vbest, bool half0)
{
    const float loss = acosf(vbest);
    const float px = yv.x, py = yv.y, pz = yv.z, pw = yv.w;
    const float qx = q.x,  qy = q.y,  qz = q.z,  qw = q.w;
    const float rw = qw*pw - qx*px - qy*py - qz*pz;
    const float rx = qw*px + qx*pw + qy*pz - qz*py;
    const float ry = qw*py - qx*pz + qy*pw + qz*px;
    const float rz = qw*pz + qx*py - qy*px + qz*pw;
    const float sgn = half0 ? 1.0f : -1.0f;
    out[b] = loss;
    reinterpret_cast<float4*>(out + B)[b]   = make_float4(xv.x*sgn, xv.y*sgn, xv.z*sgn, xv.w*sgn);
    reinterpret_cast<float4*>(out + 5*B)[b] = make_float4(rx, ry, rz, rw);
}

// monotone float<->int key (total order matching float compare; no NaNs here)
__device__ __forceinline__ int   f2ord(float f) { int b = __float_as_int(f); return b ^ ((b >> 31) & 0x7fffffff); }
__device__ __forceinline__ float ord2f(int k)   { return __int_as_float(k ^ ((k >> 31) & 0x7fffffff)); }

__global__ __launch_bounds__(256, 4)   // force <=64 regs -> 32 warps/SM
void quer_loss_kernel(const float*  __restrict__ x,
                      const float*  __restrict__ y,
                      const int*    __restrict__ n,
                      const float4* __restrict__ sym,   // [5*360] float4
                      float* __restrict__ out, int B)
{
    __shared__ float4 s4[S_MAX];   // class-4 table (5.76 KB)
    __shared__ float4 ss[4 * 12];  // classes 0..3, 12 entries each

    const int tid  = threadIdx.x;
    const int lane = tid & 31;

    for (int i = tid; i < S_MAX; i += 256)
        s4[i] = __ldg(sym + 4 * S_MAX + i);
    if (tid < 48)
        ss[tid] = __ldg(sym + (tid / 12) * S_MAX + (tid % 12));
    __syncthreads();

    const int warp = tid >> 5;
    const int base = (blockIdx.x * 8 + warp) * SPW;
    if (base >= B) return;

    const int o = lane & 7;        // owned-sample slot within warp
    const int g = lane >> 3;       // group 0..3: entries 3g..3g+2
    const int b = base + o;
    const bool valid = (b < B);
    const int bl = valid ? b : (B - 1);

    const float4 xv = __ldg(reinterpret_cast<const float4*>(x) + bl);
    const float4 yv = __ldg(reinterpret_cast<const float4*>(y) + bl);
    const int cls   = __ldg(n + bl);

    float vx, vy, vz, vw;
    compute_v(xv, yv, vx, vy, vz, vw);

    // ---- small-class phase: 4 lanes per sample, 3 entries per lane ----
    float best0 = -2.0f, best1 = -2.0f;
    int   i0 = 0, i1 = 0;
    if (cls != 4) {
        const int c = (cls == 0) ? 1 : (cls == 1) ? 2 : (cls == 2) ? 4 : 12;
        #pragma unroll
        for (int k = 0; k < 3; ++k) {
            const int s = g * 3 + k;
            if (s < c) {
                const float4 q = ss[cls * 12 + s];
                float d = vx*q.x + vy*q.y + vz*q.z + vw*q.w;
                d = fminf(fmaxf(d, -1.0f + EPS_CLP), 1.0f - EPS_CLP);
                if ( d > best0) { best0 =  d; i0 = s; }   // strict > keeps lowest s
                if (-d > best1) { best1 = -d; i1 = s; }
            }
        }
    }
    // reduce across the 4 group-lanes sharing each sample (xor 8, 16)
    #pragma unroll
    for (int off = 8; off < 32; off <<= 1) {
        const float t0 = __shfl_xor_sync(FULL, best0, off);
        const int   k0 = __shfl_xor_sync(FULL, i0,    off);
        if (t0 > best0 || (t0 == best0 && k0 < i0)) { best0 = t0; i0 = k0; }
        const float t1 = __shfl_xor_sync(FULL, best1, off);
        const int   k1 = __shfl_xor_sync(FULL, i1,    off);
        if (t1 > best1 || (t1 == best1 && k1 < i1)) { best1 = t1; i1 = k1; }
    }
    if (valid && lane < SPW && cls != 4) {
        const bool  half0 = (best0 >= best1);
        const float vbest = half0 ? best0 : best1;
        const int   sbest = half0 ? i0 : i1;
        write_result(out, B, b, xv, yv, ss[cls * 12 + sbest], vbest, half0);
    }

    // ---- cooperative phase: whole warp scans each c==360 sample ----
    unsigned m = __ballot_sync(FULL, valid && lane < SPW && cls == 4);
    while (m) {
        const int leader = __ffs(m) - 1;
        m &= m - 1;

        const float wvx = __shfl_sync(FULL, vx, leader);
        const float wvy = __shfl_sync(FULL, vy, leader);
        const float wvz = __shfl_sync(FULL, vz, leader);
        const float wvw = __shfl_sync(FULL, vw, leader);

        float bb0 = -2.0f, bb1 = -2.0f;
        int   j0 = 0, j1 = 0;
        #pragma unroll
        for (int k = 0; k < 12; ++k) {
            const int s = lane + k * 32;
            if (s < S_MAX) {                      // only k=11 partially masked
                const float4 q = s4[s];
                float d = wvx*q.x + wvy*q.y + wvz*q.z + wvw*q.w;
                d = fminf(fmaxf(d, -1.0f + EPS_CLP), 1.0f - EPS_CLP);
                if ( d > bb0) { bb0 =  d; j0 = s; }
                if (-d > bb1) { bb1 = -d; j1 = s; }
            }
        }

        // warp argmax via redux: max key, then min index among lanes at max
        const int c0 = f2ord(bb0);
        const int m0 = __reduce_max_sync(FULL, c0);
        const int s0 = __reduce_min_sync(FULL, (c0 == m0) ? j0 : 0x7fffffff);
        const int c1 = f2ord(bb1);
        const int m1 = __reduce_max_sync(FULL, c1);
        const int s1 = __reduce_min_sync(FULL, (c1 == m1) ? j1 : 0x7fffffff);

        if (lane == leader) {
            const float v0 = ord2f(m0), v1 = ord2f(m1);
            const bool  half0 = (v0 >= v1);
            const float vbest = half0 ? v0 : v1;
            const int   sbest = half0 ? s0 : s1;
            write_result(out, B, b, xv, yv, s4[sbest], vbest, half0);
        }
    }
}

extern "C" void kernel_launch(void* const* d_in, const int* in_sizes, int n_in,
                              void* d_out, int out_size)
{
    // metadata order: x[B,4], y[B,4], pred_n[B,5] (unused), n[B],
    //                 sym_qua[5,360,4], sym_mask[5,360] (unused)
    const float*  x   = (const float*) d_in[0];
    const float*  y   = (const float*) d_in[1];
    const int*    n   = (const int*)   d_in[3];
    const float4* sym = (const float4*)d_in[4];
    float* out = (float*)d_out;

    const int B = in_sizes[3];                          // 65536
    const int samples_per_block = 8 * SPW;              // 64
    const int blocks = (B + samples_per_block - 1) / samples_per_block;  // 1024
    quer_loss_kernel<<<blocks, 256>>>(x, y, n, sym, out, B);
}